// round 4
// baseline (speedup 1.0000x reference)
#include <cuda_runtime.h>
#include <cuda_bf16.h>

// Problem constants
#define BB 8
#define NN 512
#define DD 64
#define EE 32

#define JT 64                 // j's per block
#define JR 8                  // j's per warp
#define SS 8                  // i-splits
#define IT (NN / SS)          // 64 i-rows per block

#define RPB 8                 // proj: x-rows per block

// Scratch (allocation-free rule -> __device__ globals)
__device__ float g_src [BB * NN * EE];        // src[b,n,e]
__device__ float g_dstb[BB * NN * EE];        // dst[b,n,e] + be[e]
__device__ float g_part[BB * NN * SS];        // partial[b,j,s]

// ---------------------------------------------------------------------------
// Kernel 1: src = x @ We[:D], dstb = x @ We[D:] + be
// Block: 256 threads, 8 rows. Warps 0-3: src half (2 rows each), 4-7: dst half.
// We staged in smem; x rows read via broadcast LDS.128.
// ---------------------------------------------------------------------------
__global__ __launch_bounds__(256) void proj_kernel(
    const float* __restrict__ x,
    const float* __restrict__ We,
    const float* __restrict__ be)
{
    const int row0 = blockIdx.x * RPB;          // first (b*N+n) row
    __shared__ float xs [RPB][DD];              // 2 KB
    __shared__ float Wsh[2 * DD][EE];           // 16 KB

    const int tid = threadIdx.x;
    // stage We (4096 floats = 1024 float4, 4 per thread), coalesced
    #pragma unroll
    for (int k = 0; k < 4; k++)
        ((float4*)Wsh)[k * 256 + tid] = ((const float4*)We)[k * 256 + tid];
    // stage 8 x-rows (512 floats = 128 float4)
    if (tid < RPB * DD / 4)
        ((float4*)xs)[tid] = ((const float4*)(x + row0 * DD))[tid];
    __syncthreads();

    const int lane = tid & 31;                  // = e
    const int w    = tid >> 5;
    const int half = w >> 2;                    // 0 = src, 1 = dst
    const int r0   = (w & 3) * 2;               // 2 rows per warp

    const float* Wh = &Wsh[half * DD][0];
    float acc0 = half ? be[lane] : 0.0f;
    float acc1 = acc0;

    #pragma unroll
    for (int d4 = 0; d4 < DD; d4 += 4) {
        float4 xa = *(const float4*)&xs[r0    ][d4];  // broadcast LDS.128
        float4 xb = *(const float4*)&xs[r0 + 1][d4];
        #pragma unroll
        for (int k = 0; k < 4; k++) {
            float wv = Wh[(d4 + k) * EE + lane];      // conflict-free LDS
            acc0 = fmaf((&xa.x)[k], wv, acc0);
            acc1 = fmaf((&xb.x)[k], wv, acc1);
        }
    }

    float* dst = half ? g_dstb : g_src;
    dst[(row0 + r0    ) * EE + lane] = acc0;
    dst[(row0 + r0 + 1) * EE + lane] = acc1;
}

// ---------------------------------------------------------------------------
// Kernel 2: partial[b,j,s] = sum_{i in tile s, e} relu(src[b,i,e]+dstb[b,j,e])*Wr[i*E+e]
// Grid: (N/JT, B, SS). Block: 256 threads = 8 warps, warp w owns 8 j's, lane = e.
// ---------------------------------------------------------------------------
__global__ __launch_bounds__(256) void edge_reduce_kernel(
    const float* __restrict__ Wr,
    float* __restrict__ part)
{
    const int b  = blockIdx.y;
    const int jb = blockIdx.x;
    const int s  = blockIdx.z;
    const int tid  = threadIdx.x;
    const int lane = tid & 31;                  // = e
    const int w    = tid >> 5;                  // warp 0..7

    __shared__ float src_sh[IT * EE];           // 8 KB
    __shared__ float wr_sh [IT * EE];           // 8 KB
    __shared__ float dst_sh[JT * EE];           // 8 KB

    // stage dst rows (64x32), src/Wr i-tile (64x32 each), float4 coalesced
    {
        const float4* dst_g = (const float4*)(g_dstb + (b * NN + jb * JT) * EE);
        const float4* src_g = (const float4*)(g_src  + (b * NN + s  * IT) * EE);
        const float4* wr_g  = (const float4*)(Wr + s * IT * EE);
        #pragma unroll
        for (int k = 0; k < JT * EE / 4 / 256; k++) {   // 2 iters
            ((float4*)dst_sh)[k * 256 + tid] = dst_g[k * 256 + tid];
            ((float4*)src_sh)[k * 256 + tid] = src_g[k * 256 + tid];
            ((float4*)wr_sh )[k * 256 + tid] = wr_g [k * 256 + tid];
        }
    }
    __syncthreads();

    float dreg[JR], acc[JR];
    #pragma unroll
    for (int r = 0; r < JR; r++) {
        dreg[r] = dst_sh[(w * JR + r) * EE + lane];
        acc[r]  = 0.0f;
    }

    #pragma unroll 4
    for (int i = 0; i < IT; i++) {
        float sv = src_sh[i * EE + lane];        // conflict-free (stride 32)
        float wv = wr_sh [i * EE + lane];
        #pragma unroll
        for (int r = 0; r < JR; r++)
            acc[r] = fmaf(fmaxf(sv + dreg[r], 0.0f), wv, acc[r]);
    }

    // reduce across lanes (e dim + per-lane partial i-sums)
    #pragma unroll
    for (int r = 0; r < JR; r++) {
        #pragma unroll
        for (int off = 16; off; off >>= 1)
            acc[r] += __shfl_xor_sync(0xFFFFFFFFu, acc[r], off);
    }

    if (lane == 0) {
        const int j = jb * JT + w * JR;
        #pragma unroll
        for (int r = 0; r < JR; r++)
            part[(b * NN + j + r) * SS + s] = acc[r];
    }
}

// ---------------------------------------------------------------------------
// Kernel 3: out[b,j] = sum_s partial[b,j,s] + br
// ---------------------------------------------------------------------------
__global__ __launch_bounds__(256) void final_reduce_kernel(
    const float* __restrict__ part,
    const float* __restrict__ br,
    float* __restrict__ out)
{
    const int idx = blockIdx.x * 256 + threadIdx.x;   // b*N + j, 0..4095
    const float4* p = (const float4*)(part + idx * SS);
    float4 a = p[0];
    float4 c = p[1];
    out[idx] = (a.x + a.y) + (a.z + a.w) + (c.x + c.y) + (c.z + c.w) + br[0];
}

// ---------------------------------------------------------------------------
// launch
// ---------------------------------------------------------------------------
extern "C" void kernel_launch(void* const* d_in, const int* in_sizes, int n_in,
                              void* d_out, int out_size)
{
    const float* x  = (const float*)d_in[0];   // (8,512,64)
    const float* We = (const float*)d_in[1];   // (128,32)
    const float* be = (const float*)d_in[2];   // (32,)
    const float* Wr = (const float*)d_in[3];   // (16384,1)
    const float* br = (const float*)d_in[4];   // (1,)
    float* out = (float*)d_out;                // (8,512,1)

    float* partp;
    cudaGetSymbolAddress((void**)&partp, g_part);

    proj_kernel<<<BB * NN / RPB, 256>>>(x, We, be);

    dim3 grid(NN / JT, BB, SS);
    edge_reduce_kernel<<<grid, 256>>>(Wr, partp);

    final_reduce_kernel<<<BB * NN / 256, 256>>>(partp, br, out);
}

// round 5
// speedup vs baseline: 1.2150x; 1.2150x over previous
#include <cuda_runtime.h>
#include <cuda_bf16.h>

// Problem constants
#define BB 8
#define NN 512
#define DD 64
#define EE 32

#define JT 32                 // edge: j's per block   (R2 config)
#define JR 4                  // edge: j's per warp
#define SS 8                  // i-splits
#define IT (NN / SS)          // 64 i-rows per block

#define RPB 16                // proj: x-rows per block
#define RPW 4                 // proj: rows per warp

// Scratch (allocation-free rule -> __device__ globals)
__device__ float g_src [BB * NN * EE];        // src[b,n,e]
__device__ float g_dstb[BB * NN * EE];        // dst[b,n,e] + be[e]
__device__ float g_part[BB * NN * SS];        // partial[b,j,s]

// ---------------------------------------------------------------------------
// Kernel 1: src = x @ We[:D], dstb = x @ We[D:] + be
// Block: 256 threads, 16 rows. Warps 0-3: src half, 4-7: dst half; 4 rows/warp.
// We staged in smem; x rows read via broadcast LDS.128; 4 indep acc chains.
// ---------------------------------------------------------------------------
__global__ __launch_bounds__(256) void proj_kernel(
    const float* __restrict__ x,
    const float* __restrict__ We,
    const float* __restrict__ be)
{
    const int row0 = blockIdx.x * RPB;          // first (b*N+n) row
    __shared__ float xs [RPB][DD];              // 4 KB
    __shared__ float Wsh[2 * DD][EE];           // 16 KB

    const int tid = threadIdx.x;
    // stage We (4096 floats = 1024 float4, 4 per thread), coalesced
    #pragma unroll
    for (int k = 0; k < 4; k++)
        ((float4*)Wsh)[k * 256 + tid] = ((const float4*)We)[k * 256 + tid];
    // stage 16 x-rows (1024 floats = 256 float4, 1 per thread)
    ((float4*)xs)[tid] = ((const float4*)(x + row0 * DD))[tid];
    __syncthreads();

    const int lane = tid & 31;                  // = e
    const int w    = tid >> 5;
    const int half = w >> 2;                    // 0 = src, 1 = dst
    const int r0   = (w & 3) * RPW;             // 4 rows per warp

    const float* Wh = &Wsh[half * DD][0];
    const float bias = half ? be[lane] : 0.0f;

    float acc[RPW];
    #pragma unroll
    for (int r = 0; r < RPW; r++) acc[r] = bias;

    #pragma unroll
    for (int d4 = 0; d4 < DD; d4 += 4) {
        float4 xv[RPW];
        #pragma unroll
        for (int r = 0; r < RPW; r++)
            xv[r] = *(const float4*)&xs[r0 + r][d4];  // broadcast LDS.128
        #pragma unroll
        for (int k = 0; k < 4; k++) {
            float wv = Wh[(d4 + k) * EE + lane];      // conflict-free LDS
            #pragma unroll
            for (int r = 0; r < RPW; r++)
                acc[r] = fmaf((&xv[r].x)[k], wv, acc[r]);
        }
    }

    float* dst = half ? g_dstb : g_src;
    #pragma unroll
    for (int r = 0; r < RPW; r++)
        dst[(row0 + r0 + r) * EE + lane] = acc[r];    // coalesced 128B stores
}

// ---------------------------------------------------------------------------
// Kernel 2 (R2 config): partial[b,j,s] =
//   sum_{i in tile s, e} relu(src[b,i,e]+dstb[b,j,e]) * Wr[i*E+e]
// Grid: (N/32, B, 8) = 1024 blocks. Block: 256 threads = 8 warps,
// warp owns 4 j's, lane = e. One 64-row i-tile per block.
// ---------------------------------------------------------------------------
__global__ __launch_bounds__(256) void edge_reduce_kernel(
    const float* __restrict__ Wr,
    float* __restrict__ part)
{
    const int b  = blockIdx.y;
    const int jb = blockIdx.x;
    const int s  = blockIdx.z;
    const int tid  = threadIdx.x;
    const int lane = tid & 31;                  // = e
    const int w    = tid >> 5;                  // warp 0..7

    __shared__ float src_sh[IT * EE];           // 8 KB
    __shared__ float wr_sh [IT * EE];           // 8 KB
    __shared__ float dst_sh[JT * EE];           // 4 KB

    {
        const float4* dst_g = (const float4*)(g_dstb + (b * NN + jb * JT) * EE);
        ((float4*)dst_sh)[tid] = dst_g[tid];    // 256 float4 = 1 per thread

        const float4* src_g = (const float4*)(g_src + (b * NN + s * IT) * EE);
        const float4* wr_g  = (const float4*)(Wr + s * IT * EE);
        #pragma unroll
        for (int k = 0; k < IT * EE / 4 / 256; k++) {   // 2 iters
            ((float4*)src_sh)[k * 256 + tid] = src_g[k * 256 + tid];
            ((float4*)wr_sh )[k * 256 + tid] = wr_g [k * 256 + tid];
        }
    }
    __syncthreads();

    float dreg[JR], acc[JR];
    #pragma unroll
    for (int r = 0; r < JR; r++) {
        dreg[r] = dst_sh[(w * JR + r) * EE + lane];
        acc[r]  = 0.0f;
    }

    #pragma unroll 8
    for (int i = 0; i < IT; i++) {
        float sv = src_sh[i * EE + lane];        // conflict-free (stride 32)
        float wv = wr_sh [i * EE + lane];
        #pragma unroll
        for (int r = 0; r < JR; r++)
            acc[r] = fmaf(fmaxf(sv + dreg[r], 0.0f), wv, acc[r]);
    }

    // reduce across lanes (e dim + per-lane partial i-sums)
    #pragma unroll
    for (int r = 0; r < JR; r++) {
        #pragma unroll
        for (int off = 16; off; off >>= 1)
            acc[r] += __shfl_xor_sync(0xFFFFFFFFu, acc[r], off);
    }

    if (lane == 0) {
        const int j = jb * JT + w * JR;
        #pragma unroll
        for (int r = 0; r < JR; r++)
            part[(b * NN + j + r) * SS + s] = acc[r];
    }
}

// ---------------------------------------------------------------------------
// Kernel 3: out[b,j] = sum_s partial[b,j,s] + br
// ---------------------------------------------------------------------------
__global__ __launch_bounds__(256) void final_reduce_kernel(
    const float* __restrict__ part,
    const float* __restrict__ br,
    float* __restrict__ out)
{
    const int idx = blockIdx.x * 256 + threadIdx.x;   // b*N + j, 0..4095
    const float4* p = (const float4*)(part + idx * SS);
    float4 a = p[0];
    float4 c = p[1];
    out[idx] = (a.x + a.y) + (a.z + a.w) + (c.x + c.y) + (c.z + c.w) + br[0];
}

// ---------------------------------------------------------------------------
// launch
// ---------------------------------------------------------------------------
extern "C" void kernel_launch(void* const* d_in, const int* in_sizes, int n_in,
                              void* d_out, int out_size)
{
    const float* x  = (const float*)d_in[0];   // (8,512,64)
    const float* We = (const float*)d_in[1];   // (128,32)
    const float* be = (const float*)d_in[2];   // (32,)
    const float* Wr = (const float*)d_in[3];   // (16384,1)
    const float* br = (const float*)d_in[4];   // (1,)
    float* out = (float*)d_out;                // (8,512,1)

    float* partp;
    cudaGetSymbolAddress((void**)&partp, g_part);

    proj_kernel<<<BB * NN / RPB, 256>>>(x, We, be);

    dim3 grid(NN / JT, BB, SS);
    edge_reduce_kernel<<<grid, 256>>>(Wr, partp);

    final_reduce_kernel<<<BB * NN / 256, 256>>>(partp, br, out);
}